// round 12
// baseline (speedup 1.0000x reference)
#include <cuda_runtime.h>
#include <cuda_bf16.h>
#include <cstdint>

#define B_    128
#define T_    512
#define D_    256
#define H_    1024
#define G4_   4096
#define Z_    128
#define NBLK  128
#define NTHR  512        // 16 warps (4 per SMSP)
#define XROW  512        // g_xi row elems (8 chunks * 64)
#define HROW  2048       // g_hx row elems (32 chunks * 64)

// dynamic smem map (bytes)
#define SM_B      1024                 // 80 ktiles * 2048 B (fragment-order) = 160 KB
#define SM_A      164864               // 4 stages * 16384 B (128 rows * 128 B swizzled)
#define SM_GS     (SM_A + 2 * 16384)   // epilogue reduction scratch (16 KB, stages 2-3)
#define SM_SIZE   230400

#define SWZ(o) ((o) ^ ((((o) >> 3) & 0x70)))

// ---------------- persistent device state ----------------
__device__ __align__(16) __nv_bfloat16 g_Ub[(size_t)NBLK * 81920];     // frag-order B
__device__ __align__(16) __nv_bfloat16 g_xi[(size_t)B_ * T_ * XROW];   // x hi/lo
__device__ __align__(16) __nv_bfloat16 g_hx[2][(size_t)B_ * HROW];     // h hi/lo
__device__ float         g_h32[(size_t)B_ * H_];
__device__ unsigned int  g_bar;

// ---------------- helpers ----------------
__device__ __forceinline__ uint32_t smem_u32(const void* p) {
    uint32_t a;
    asm("{ .reg .u64 t; cvta.to.shared.u64 t, %1; cvt.u32.u64 %0, t; }" : "=r"(a) : "l"(p));
    return a;
}
__device__ __forceinline__ void cp_async16(uint32_t dst, const void* src) {
    asm volatile("cp.async.cg.shared.global [%0], [%1], 16;" :: "r"(dst), "l"(src) : "memory");
}
__device__ __forceinline__ void ldsm4(uint32_t* r, uint32_t addr) {
    asm volatile("ldmatrix.sync.aligned.m8n8.x4.shared.b16 {%0,%1,%2,%3}, [%4];"
                 : "=r"(r[0]), "=r"(r[1]), "=r"(r[2]), "=r"(r[3]) : "r"(addr));
}
__device__ __forceinline__ void mma_bf16(float* d, const uint32_t* a, uint32_t b0, uint32_t b1) {
    asm volatile(
        "mma.sync.aligned.m16n8k16.row.col.f32.bf16.bf16.f32 "
        "{%0,%1,%2,%3}, {%4,%5,%6,%7}, {%8,%9}, {%0,%1,%2,%3};"
        : "+f"(d[0]), "+f"(d[1]), "+f"(d[2]), "+f"(d[3])
        : "r"(a[0]), "r"(a[1]), "r"(a[2]), "r"(a[3]), "r"(b0), "r"(b1));
}
__device__ __forceinline__ void st_cg_u32(void* p, uint32_t v) {
    asm volatile("st.global.cg.u32 [%0], %1;" :: "l"(p), "r"(v) : "memory");
}
__device__ __forceinline__ float sigmoid_f(float x) { return 1.0f / (1.0f + expf(-x)); }
__device__ __forceinline__ float softplus_f(float x) {
    return fmaxf(x, 0.0f) + log1pf(expf(-fabsf(x)));
}

// ---------------- prep kernels ----------------
__global__ void reset_kernel() {
    int i = blockIdx.x * blockDim.x + threadIdx.x;
    if (i == 0) g_bar = 0u;
    uint4* p = (uint4*)&g_hx[0][0];
    for (int e = i; e < (int)((size_t)B_ * HROW * 2 / 16); e += gridDim.x * blockDim.x)
        p[e] = make_uint4(0, 0, 0, 0);
}

// x[B,T,D] fp32 -> g_xi: per row, 8 chunks of [16hi|16lo|16hi|16lo] (64 elems)
__global__ void xprep_kernel(const float* __restrict__ x) {
    size_t e = (size_t)blockIdx.x * blockDim.x + threadIdx.x;   // < B*T*D
    float v = x[e];
    __nv_bfloat16 hi = __float2bfloat16(v);
    __nv_bfloat16 lo = __float2bfloat16(v - __bfloat162float(hi));
    size_t bt = e >> 8;
    int k = (int)(e & 255);
    int c = k >> 5, sub = (k >> 4) & 1, pos = k & 15;
    __nv_bfloat16* d = g_xi + bt * XROW + c * 64 + sub * 32 + pos;
    d[0] = hi; d[16] = lo;
}

// W[256,4096], U[1024,4096] -> per-block fragment-order B images.
__global__ void uprep_kernel(const float* __restrict__ W, const float* __restrict__ U) {
    size_t id = (size_t)blockIdx.x * blockDim.x + threadIdx.x;   // < 128*40960
    int bid = (int)(id / 40960);
    int r   = (int)(id % 40960);
    int kt   = r >> 9;
    int r2   = r & 511;
    int half = r2 >> 8;
    int lane = (r2 >> 3) & 31;
    int e    = r2 & 7;
    int nip = e >> 2, rg = (e >> 1) & 1, i = e & 1;
    int k = kt * 16 + (lane & 3) * 2 + rg * 8 + i;
    int n = (half * 2 + nip) * 8 + (lane >> 2);
    int gcol = (n >> 3) * H_ + bid * 8 + (n & 7);
    float v = (k < 256) ? W[(size_t)k * G4_ + gcol]
                        : U[(size_t)(k - 256) * G4_ + gcol];
    __nv_bfloat16 hi = __float2bfloat16(v);
    __nv_bfloat16 lo = __float2bfloat16(v - __bfloat162float(hi));
    __nv_bfloat16* base = g_Ub + (size_t)bid * 81920 +
                          (size_t)((kt * 2 + half) * 2) * 256 + lane * 8 + e;
    base[0]   = hi;     // hl=0
    base[256] = lo;     // hl=1
}

// ---------------- A chunk issue (one 32-k chunk, 16 KB, 512 threads) ----------------
__device__ __forceinline__ void issue_chunk(uint32_t sb, int t, int ig, int tid) {
    uint32_t dstb = sb + SM_A + (ig & 3) * 16384;
    const int row = tid >> 2;
    const int qb  = (tid & 3) * 32;
    const char* srcrow;
    if (ig < 8)
        srcrow = (const char*)(g_xi + ((size_t)row * T_ + t) * XROW) + ig * 128 + qb;
    else
        srcrow = (const char*)(g_hx[t & 1] + (size_t)row * HROW) + (ig - 8) * 128 + qb;
    cp_async16(dstb + SWZ(row * 128 + qb),      srcrow);
    cp_async16(dstb + SWZ(row * 128 + qb + 16), srcrow + 16);
    asm volatile("cp.async.commit_group;" ::: "memory");
}

// ---------------- main persistent kernel ----------------
__global__ void __launch_bounds__(NTHR, 1)
lstm_kernel(const float* __restrict__ bias)
{
    extern __shared__ char smem[];
    const uint32_t sb = smem_u32(smem);
    const int tid  = threadIdx.x;
    const int w    = tid >> 5;
    const int lane = tid & 31;
    const int m    = w & 7;            // m-tile: rows [16m, 16m+16)
    const int wk   = w >> 3;           // k-half (sub) ownership
    const int bid  = blockIdx.x;
    const int j0   = bid * 8;

    // Load resident fragment-order B (160 KB) once.
    {
        const char* src = (const char*)(g_Ub + (size_t)bid * 81920);
        for (int i = tid; i < 10240; i += NTHR)
            cp_async16(sb + SM_B + i * 16, src + (size_t)i * 16);
        asm volatile("cp.async.commit_group;\n\tcp.async.wait_group 0;" ::: "memory");
    }
    __syncthreads();

    // per-thread constants
    const int lm_row = (lane & 7) + ((lane >> 3) & 1) * 8;
    const int lm_k   = (lane >> 4) & 1;
    const uint32_t ro_base = (uint32_t)(m * 16 + lm_row) * 128 + wk * 64 + lm_k * 16;

    float bR[4][2];
#pragma unroll
    for (int g = 0; g < 4; g++)
#pragma unroll
        for (int p = 0; p < 2; p++)
            bR[g][p] = bias[g * H_ + j0 + (lane & 3) * 2 + p];

    float creg[4];
#pragma unroll
    for (int i = 0; i < 4; i++) creg[i] = 0.f;

    // prologue: x-chunks 0,1 of t=0
    issue_chunk(sb, 0, 0, tid);
    issue_chunk(sb, 0, 1, tid);

    for (int t = 0; t < T_; t++) {
        float acc[4][4];
#pragma unroll
        for (int nt = 0; nt < 4; nt++)
#pragma unroll
            for (int i = 0; i < 4; i++) acc[nt][i] = 0.f;

        for (int gg = 0; gg < 20; gg++) {
            __syncthreads();   // guards stage reuse (prev iter reads done)

            // issue chunks 2gg+2, 2gg+3 (cross-step x-prefetch at the tail)
#pragma unroll
            for (int c = 0; c < 2; c++) {
                const int ig = 2 * gg + 2 + c;
                if (ig < 40)            issue_chunk(sb, t, ig, tid);
                else if (t + 1 < T_)    issue_chunk(sb, t + 1, ig - 40, tid);
                else asm volatile("cp.async.commit_group;" ::: "memory");
            }

            asm volatile("cp.async.wait_group 2;" ::: "memory");  // chunks 2gg,2gg+1 ready

            // consume chunks 2gg, 2gg+1 — this warp's k-half only
#pragma unroll
            for (int c = 0; c < 2; c++) {
                const int chunk = 2 * gg + c;
                const uint32_t stA = sb + SM_A + (chunk & 3) * 16384;
                uint32_t ah[4], al[4];
                ldsm4(ah, stA + SWZ(ro_base));
                ldsm4(al, stA + SWZ(ro_base + 32));
                const int kt = chunk * 2 + wk;
                const char* bb = smem + SM_B + kt * 2048 + lane * 16;
                uint4 h0 = *(const uint4*)(bb);
                uint4 l0 = *(const uint4*)(bb + 512);
                uint4 h1 = *(const uint4*)(bb + 1024);
                uint4 l1 = *(const uint4*)(bb + 1536);
                uint32_t bh[4][2] = {{h0.x, h0.y}, {h0.z, h0.w}, {h1.x, h1.y}, {h1.z, h1.w}};
                uint32_t bl[4][2] = {{l0.x, l0.y}, {l0.z, l0.w}, {l1.x, l1.y}, {l1.z, l1.w}};
#pragma unroll
                for (int nt = 0; nt < 4; nt++) {
                    mma_bf16(acc[nt], ah, bh[nt][0], bh[nt][1]);
                    mma_bf16(acc[nt], al, bh[nt][0], bh[nt][1]);
                    mma_bf16(acc[nt], ah, bl[nt][0], bl[nt][1]);
                }
            }
        }

        // ---- k-half reduction through smem (stages 2,3 region, now free) ----
        __syncthreads();
        float* Gs = (float*)(smem + SM_GS);
        if (wk == 1) {
#pragma unroll
            for (int nt = 0; nt < 4; nt++)
                *(float4*)(Gs + ((m * 4 + nt) * 32 + lane) * 4) = *(const float4*)acc[nt];
        }
        __syncthreads();

        // ---- epilogue (wk=0 warps): reduce, bias, cell update, write h ----
        if (wk == 0) {
#pragma unroll
            for (int nt = 0; nt < 4; nt++) {
                float4 o = *(const float4*)(Gs + ((m * 4 + nt) * 32 + lane) * 4);
                acc[nt][0] += o.x; acc[nt][1] += o.y;
                acc[nt][2] += o.z; acc[nt][3] += o.w;
            }
            char* hwB = (char*)(g_hx[(t + 1) & 1]);
            const int cbyte = (j0 >> 5) * 128 + ((j0 >> 4) & 1) * 64 +
                              ((j0 & 15) + (lane & 3) * 2) * 2;
#pragma unroll
            for (int rs = 0; rs < 2; rs++) {
                const int row = m * 16 + (lane >> 2) + rs * 8;
                __nv_bfloat16 hhi[2], hlo[2];
#pragma unroll
                for (int p = 0; p < 2; p++) {
                    const int ai = rs * 2 + p;
                    float gi = acc[0][ai] + bR[0][p];
                    float gf = acc[1][ai] + bR[1][p];
                    float gg2 = acc[2][ai] + bR[2][p];
                    float go = acc[3][ai] + bR[3][p];
                    float iv = sigmoid_f(gi), fv = sigmoid_f(gf), ov = sigmoid_f(go);
                    float gv = softplus_f(gg2);
                    const int ci = rs * 2 + p;
                    float cn = fv * creg[ci] + iv * gv;
                    creg[ci] = cn;
                    float hn = ov * softplus_f(cn);
                    hhi[p] = __float2bfloat16(hn);
                    hlo[p] = __float2bfloat16(hn - __bfloat162float(hhi[p]));
                    if (t == T_ - 1)
                        g_h32[(size_t)row * H_ + j0 + (lane & 3) * 2 + p] = hn;
                }
                char* base = hwB + (size_t)row * 4096 + cbyte;
                uint32_t phi = (uint32_t)__bfloat16_as_ushort(hhi[0]) |
                               ((uint32_t)__bfloat16_as_ushort(hhi[1]) << 16);
                uint32_t plo = (uint32_t)__bfloat16_as_ushort(hlo[0]) |
                               ((uint32_t)__bfloat16_as_ushort(hlo[1]) << 16);
                st_cg_u32(base,      phi);
                st_cg_u32(base + 32, plo);
            }
        }

        // ---- grid barrier ----
        __syncthreads();
        if (tid == 0) {
            __threadfence();
            atomicAdd(&g_bar, 1u);
            const unsigned target = (unsigned)(t + 1) * (unsigned)NBLK;
            while (*(volatile unsigned*)&g_bar < target) { __nanosleep(32); }
            __threadfence();
        }
        __syncthreads();
    }
}

// ---------------- final projections (fp32) ----------------
__global__ void __launch_bounds__(Z_)
proj_kernel(const float* __restrict__ Wm, const float* __restrict__ bm,
            const float* __restrict__ Wv, const float* __restrict__ bv,
            const float* __restrict__ eps, float* __restrict__ out)
{
    __shared__ float hs[H_];
    const int b = blockIdx.x;
    const int z = threadIdx.x;
    const float* hrow = g_h32 + (size_t)b * H_;
    for (int k = z; k < H_; k += Z_) hs[k] = hrow[k];
    __syncthreads();

    float am = bm[z];
    float av = bv[z];
#pragma unroll 4
    for (int k = 0; k < H_; k++) {
        float hk = hs[k];
        am += hk * Wm[(size_t)k * Z_ + z];
        av += hk * Wv[(size_t)k * Z_ + z];
    }
    float zz = am + eps[(size_t)b * Z_ + z] * expf(0.5f * av);
    out[(size_t)b * Z_ + z]                 = am;
    out[(size_t)(B_ * Z_) + b * Z_ + z]     = av;
    out[(size_t)(2 * B_ * Z_) + b * Z_ + z] = zz;
}

// ---------------------------------------------------------------------------
extern "C" void kernel_launch(void* const* d_in, const int* in_sizes, int n_in,
                              void* d_out, int out_size)
{
    const float* x   = (const float*)d_in[0];
    const float* W   = (const float*)d_in[1];
    const float* U   = (const float*)d_in[2];
    const float* b   = (const float*)d_in[3];
    const float* Wm  = (const float*)d_in[4];
    const float* bm  = (const float*)d_in[5];
    const float* Wv  = (const float*)d_in[6];
    const float* bv  = (const float*)d_in[7];
    const float* eps = (const float*)d_in[8];
    float* out = (float*)d_out;

    cudaFuncSetAttribute(lstm_kernel, cudaFuncAttributeMaxDynamicSharedMemorySize, SM_SIZE);

    reset_kernel<<<256, 256>>>();
    xprep_kernel<<<(B_ * T_ * D_) / 256, 256>>>(x);
    uprep_kernel<<<(NBLK * 40960) / 256, 256>>>(W, U);
    lstm_kernel<<<NBLK, NTHR, SM_SIZE>>>(b);
    proj_kernel<<<B_, Z_>>>(Wm, bm, Wv, bv, eps, out);
}

// round 13
// speedup vs baseline: 1.9027x; 1.9027x over previous
#include <cuda_runtime.h>
#include <cuda_bf16.h>
#include <cstdint>

#define B_    128
#define T_    512
#define D_    256
#define H_    1024
#define G4_   4096
#define Z_    128
#define NBLK  128
#define NTHR  256        // 8 warps; warp w owns rows [16w,16w+16)
#define XROW  512        // g_xi row elems (8 chunks * 64)
#define HROW  2048       // g_hx row elems (32 chunks * 64)

// dynamic smem map (bytes)
#define SM_B      1024                 // 80 ktiles * 2048 B (fragment-order) = 160 KB
#define SM_A      164864               // 8 warps * 4 slots * 2048 B = 64 KB (warp-private rings)
#define SM_SIZE   230400

#define SWZ(o) ((o) ^ ((((o) >> 3) & 0x70)))

// ---------------- persistent device state ----------------
__device__ __align__(16) __nv_bfloat16 g_Ub[(size_t)NBLK * 81920];     // frag-order B
__device__ __align__(16) __nv_bfloat16 g_xi[(size_t)B_ * T_ * XROW];   // x hi/lo
__device__ __align__(16) __nv_bfloat16 g_hx[2][(size_t)B_ * HROW];     // h hi/lo
__device__ float         g_h32[(size_t)B_ * H_];
__device__ unsigned int  g_bar;

// ---------------- helpers ----------------
__device__ __forceinline__ uint32_t smem_u32(const void* p) {
    uint32_t a;
    asm("{ .reg .u64 t; cvta.to.shared.u64 t, %1; cvt.u32.u64 %0, t; }" : "=r"(a) : "l"(p));
    return a;
}
__device__ __forceinline__ void cp_async16(uint32_t dst, const void* src) {
    asm volatile("cp.async.cg.shared.global [%0], [%1], 16;" :: "r"(dst), "l"(src) : "memory");
}
__device__ __forceinline__ void ldsm4(uint32_t* r, uint32_t addr) {
    asm volatile("ldmatrix.sync.aligned.m8n8.x4.shared.b16 {%0,%1,%2,%3}, [%4];"
                 : "=r"(r[0]), "=r"(r[1]), "=r"(r[2]), "=r"(r[3]) : "r"(addr));
}
__device__ __forceinline__ void mma_bf16(float* d, const uint32_t* a, uint32_t b0, uint32_t b1) {
    asm volatile(
        "mma.sync.aligned.m16n8k16.row.col.f32.bf16.bf16.f32 "
        "{%0,%1,%2,%3}, {%4,%5,%6,%7}, {%8,%9}, {%0,%1,%2,%3};"
        : "+f"(d[0]), "+f"(d[1]), "+f"(d[2]), "+f"(d[3])
        : "r"(a[0]), "r"(a[1]), "r"(a[2]), "r"(a[3]), "r"(b0), "r"(b1));
}
__device__ __forceinline__ void st_cg_u32(void* p, uint32_t v) {
    asm volatile("st.global.cg.u32 [%0], %1;" :: "l"(p), "r"(v) : "memory");
}
__device__ __forceinline__ float sigmoid_f(float x) { return 1.0f / (1.0f + expf(-x)); }
__device__ __forceinline__ float softplus_f(float x) {
    return fmaxf(x, 0.0f) + log1pf(expf(-fabsf(x)));
}

// ---------------- prep kernels ----------------
__global__ void reset_kernel() {
    int i = blockIdx.x * blockDim.x + threadIdx.x;
    if (i == 0) g_bar = 0u;
    uint4* p = (uint4*)&g_hx[0][0];
    for (int e = i; e < (int)((size_t)B_ * HROW * 2 / 16); e += gridDim.x * blockDim.x)
        p[e] = make_uint4(0, 0, 0, 0);
}

// x[B,T,D] fp32 -> g_xi: per row, 8 chunks of [16hi|16lo|16hi|16lo] (64 elems)
__global__ void xprep_kernel(const float* __restrict__ x) {
    size_t e = (size_t)blockIdx.x * blockDim.x + threadIdx.x;   // < B*T*D
    float v = x[e];
    __nv_bfloat16 hi = __float2bfloat16(v);
    __nv_bfloat16 lo = __float2bfloat16(v - __bfloat162float(hi));
    size_t bt = e >> 8;
    int k = (int)(e & 255);
    int c = k >> 5, sub = (k >> 4) & 1, pos = k & 15;
    __nv_bfloat16* d = g_xi + bt * XROW + c * 64 + sub * 32 + pos;
    d[0] = hi; d[16] = lo;
}

// W[256,4096], U[1024,4096] -> per-block fragment-order B images.
__global__ void uprep_kernel(const float* __restrict__ W, const float* __restrict__ U) {
    size_t id = (size_t)blockIdx.x * blockDim.x + threadIdx.x;   // < 128*40960
    int bid = (int)(id / 40960);
    int r   = (int)(id % 40960);
    int kt   = r >> 9;
    int r2   = r & 511;
    int half = r2 >> 8;
    int lane = (r2 >> 3) & 31;
    int e    = r2 & 7;
    int nip = e >> 2, rg = (e >> 1) & 1, i = e & 1;
    int k = kt * 16 + (lane & 3) * 2 + rg * 8 + i;
    int n = (half * 2 + nip) * 8 + (lane >> 2);
    int gcol = (n >> 3) * H_ + bid * 8 + (n & 7);
    float v = (k < 256) ? W[(size_t)k * G4_ + gcol]
                        : U[(size_t)(k - 256) * G4_ + gcol];
    __nv_bfloat16 hi = __float2bfloat16(v);
    __nv_bfloat16 lo = __float2bfloat16(v - __bfloat162float(hi));
    __nv_bfloat16* base = g_Ub + (size_t)bid * 81920 +
                          (size_t)((kt * 2 + half) * 2) * 256 + lane * 8 + e;
    base[0]   = hi;     // hl=0
    base[256] = lo;     // hl=1
}

// ---------------- warp-local A chunk issue (16 rows, 2 KB) ----------------
// lane: row16 = lane & 15, half hh = (lane>>4)*64; 4 x 16B each.
__device__ __forceinline__ void issue_chunk_w(uint32_t wbase, int t, int ig,
                                              int w, int lane) {
    const int row16 = lane & 15;
    const int hh    = (lane >> 4) * 64;
    uint32_t slot = wbase + (ig & 3) * 2048;
    const char* srcrow;
    if (ig < 8)
        srcrow = (const char*)(g_xi + ((size_t)(w * 16 + row16) * T_ + t) * XROW) +
                 ig * 128 + hh;
    else
        srcrow = (const char*)(g_hx[t & 1] + (size_t)(w * 16 + row16) * HROW) +
                 (ig - 8) * 128 + hh;
#pragma unroll
    for (int q = 0; q < 4; q++)
        cp_async16(slot + SWZ(row16 * 128 + hh + q * 16), srcrow + q * 16);
    asm volatile("cp.async.commit_group;" ::: "memory");
}

// ---------------- main persistent kernel ----------------
__global__ void __launch_bounds__(NTHR, 1)
lstm_kernel(const float* __restrict__ bias)
{
    extern __shared__ char smem[];
    const uint32_t sb = smem_u32(smem);
    const int tid  = threadIdx.x;
    const int w    = tid >> 5;          // 0..7, owns rows [16w, 16w+16)
    const int lane = tid & 31;
    const int bid  = blockIdx.x;
    const int j0   = bid * 8;
    const uint32_t wbase = sb + SM_A + w * 8192;   // warp-private 4-slot ring

    // Load resident fragment-order B (160 KB) once.
    {
        const char* src = (const char*)(g_Ub + (size_t)bid * 81920);
        for (int i = tid; i < 10240; i += NTHR)
            cp_async16(sb + SM_B + i * 16, src + (size_t)i * 16);
        asm volatile("cp.async.commit_group;\n\tcp.async.wait_group 0;" ::: "memory");
    }
    __syncthreads();

    // per-thread constants (warp-local slot addressing: no w*16 row offset)
    const int lm_row = (lane & 7) + ((lane >> 3) & 1) * 8;   // 0..15
    const int lm_k   = (lane >> 4) & 1;

    float bR[4][2];
#pragma unroll
    for (int g = 0; g < 4; g++)
#pragma unroll
        for (int p = 0; p < 2; p++)
            bR[g][p] = bias[g * H_ + j0 + (lane & 3) * 2 + p];

    float creg[4];
#pragma unroll
    for (int i = 0; i < 4; i++) creg[i] = 0.f;

    // prologue: x-chunks 0..2 of t=0 into slots 0..2
#pragma unroll
    for (int p = 0; p < 3; p++) issue_chunk_w(wbase, 0, p, w, lane);

    for (int t = 0; t < T_; t++) {
        float acc[4][4];
#pragma unroll
        for (int nt = 0; nt < 4; nt++)
#pragma unroll
            for (int i = 0; i < 4; i++) acc[nt][i] = 0.f;

        for (int g = 0; g < 40; g++) {
            // issue chunk g+3 into slot (g+3)&3 (its old occupant g-1 was
            // consumed by this warp last iteration — program order, no sync)
            const int ig = g + 3;
            if (ig < 40)         issue_chunk_w(wbase, t, ig, w, lane);
            else if (t + 1 < T_) issue_chunk_w(wbase, t + 1, ig - 40, w, lane);
            else asm volatile("cp.async.commit_group;" ::: "memory");

            // chunk g arrived when at most 3 newer groups pending
            asm volatile("cp.async.wait_group 3;" ::: "memory");
            __syncwarp();

            const uint32_t stA = wbase + (g & 3) * 2048;
#pragma unroll
            for (int sub = 0; sub < 2; sub++) {
                uint32_t ah[4], al[4];
                uint32_t ro = (uint32_t)lm_row * 128 + sub * 64 + lm_k * 16;
                ldsm4(ah, stA + SWZ(ro));
                ldsm4(al, stA + SWZ(ro + 32));
                const int kt = g * 2 + sub;
                const char* bb = smem + SM_B + kt * 2048 + lane * 16;
                uint4 h0 = *(const uint4*)(bb);            // hi, ntiles 0,1
                uint4 l0 = *(const uint4*)(bb + 512);      // lo, ntiles 0,1
                uint4 h1 = *(const uint4*)(bb + 1024);     // hi, ntiles 2,3
                uint4 l1 = *(const uint4*)(bb + 1536);     // lo, ntiles 2,3
                uint32_t bh[4][2] = {{h0.x, h0.y}, {h0.z, h0.w}, {h1.x, h1.y}, {h1.z, h1.w}};
                uint32_t bl[4][2] = {{l0.x, l0.y}, {l0.z, l0.w}, {l1.x, l1.y}, {l1.z, l1.w}};
#pragma unroll
                for (int nt = 0; nt < 4; nt++) {
                    mma_bf16(acc[nt], ah, bh[nt][0], bh[nt][1]);
                    mma_bf16(acc[nt], al, bh[nt][0], bh[nt][1]);
                    mma_bf16(acc[nt], ah, bl[nt][0], bl[nt][1]);
                }
            }
        }

        // ---- epilogue: cell update, fully lane-local (16 rows per warp) ----
        {
            char* hwB = (char*)(g_hx[(t + 1) & 1]);
            const int cbyte = (j0 >> 5) * 128 + ((j0 >> 4) & 1) * 64 +
                              ((j0 & 15) + (lane & 3) * 2) * 2;
#pragma unroll
            for (int rs = 0; rs < 2; rs++) {
                const int row = w * 16 + (lane >> 2) + rs * 8;
                __nv_bfloat16 hhi[2], hlo[2];
#pragma unroll
                for (int p = 0; p < 2; p++) {
                    const int ai = rs * 2 + p;
                    float gi = acc[0][ai] + bR[0][p];
                    float gf = acc[1][ai] + bR[1][p];
                    float gg = acc[2][ai] + bR[2][p];
                    float go = acc[3][ai] + bR[3][p];
                    float iv = sigmoid_f(gi), fv = sigmoid_f(gf), ov = sigmoid_f(go);
                    float gv = softplus_f(gg);
                    const int ci = rs * 2 + p;
                    float cn = fv * creg[ci] + iv * gv;
                    creg[ci] = cn;
                    float hn = ov * softplus_f(cn);
                    hhi[p] = __float2bfloat16(hn);
                    hlo[p] = __float2bfloat16(hn - __bfloat162float(hhi[p]));
                    if (t == T_ - 1)
                        g_h32[(size_t)row * H_ + j0 + (lane & 3) * 2 + p] = hn;
                }
                char* base = hwB + (size_t)row * 4096 + cbyte;
                uint32_t phi = (uint32_t)__bfloat16_as_ushort(hhi[0]) |
                               ((uint32_t)__bfloat16_as_ushort(hhi[1]) << 16);
                uint32_t plo = (uint32_t)__bfloat16_as_ushort(hlo[0]) |
                               ((uint32_t)__bfloat16_as_ushort(hlo[1]) << 16);
                st_cg_u32(base,      phi);
                st_cg_u32(base + 32, plo);
            }
        }

        // ---- grid barrier (only block-wide sync per step) ----
        __syncthreads();
        if (tid == 0) {
            __threadfence();
            atomicAdd(&g_bar, 1u);
            const unsigned target = (unsigned)(t + 1) * (unsigned)NBLK;
            while (*(volatile unsigned*)&g_bar < target) { __nanosleep(32); }
            __threadfence();
        }
        __syncthreads();
    }
}

// ---------------- final projections (fp32) ----------------
__global__ void __launch_bounds__(Z_)
proj_kernel(const float* __restrict__ Wm, const float* __restrict__ bm,
            const float* __restrict__ Wv, const float* __restrict__ bv,
            const float* __restrict__ eps, float* __restrict__ out)
{
    __shared__ float hs[H_];
    const int b = blockIdx.x;
    const int z = threadIdx.x;
    const float* hrow = g_h32 + (size_t)b * H_;
    for (int k = z; k < H_; k += Z_) hs[k] = hrow[k];
    __syncthreads();

    float am = bm[z];
    float av = bv[z];
#pragma unroll 4
    for (int k = 0; k < H_; k++) {
        float hk = hs[k];
        am += hk * Wm[(size_t)k * Z_ + z];
        av += hk * Wv[(size_t)k * Z_ + z];
    }
    float zz = am + eps[(size_t)b * Z_ + z] * expf(0.5f * av);
    out[(size_t)b * Z_ + z]                 = am;
    out[(size_t)(B_ * Z_) + b * Z_ + z]     = av;
    out[(size_t)(2 * B_ * Z_) + b * Z_ + z] = zz;
}

// ---------------------------------------------------------------------------
extern "C" void kernel_launch(void* const* d_in, const int* in_sizes, int n_in,
                              void* d_out, int out_size)
{
    const float* x   = (const float*)d_in[0];
    const float* W   = (const float*)d_in[1];
    const float* U   = (const float*)d_in[2];
    const float* b   = (const float*)d_in[3];
    const float* Wm  = (const float*)d_in[4];
    const float* bm  = (const float*)d_in[5];
    const float* Wv  = (const float*)d_in[6];
    const float* bv  = (const float*)d_in[7];
    const float* eps = (const float*)d_in[8];
    float* out = (float*)d_out;

    cudaFuncSetAttribute(lstm_kernel, cudaFuncAttributeMaxDynamicSharedMemorySize, SM_SIZE);

    reset_kernel<<<256, 256>>>();
    xprep_kernel<<<(B_ * T_ * D_) / 256, 256>>>(x);
    uprep_kernel<<<(NBLK * 40960) / 256, 256>>>(W, U);
    lstm_kernel<<<NBLK, NTHR, SM_SIZE>>>(b);
    proj_kernel<<<B_, Z_>>>(Wm, bm, Wv, bv, eps, out);
}